// round 16
// baseline (speedup 1.0000x reference)
#include <cuda_runtime.h>
#include <cuda_fp16.h>
#include <cstdint>

typedef __half fp16;

#define BATCH 8192
#define UNITS 256
#define NACT  16
#define HID   8
#define HCOLS (UNITS * HID)   // 2048

#define MT 128        // batch rows per CTA
#define NTC 128       // h-cols per CTA
#define KC 64         // k per chunk
#define NTHR 512
#define A_TILE_B (MT * KC * 2)    // 16384 B per tile
#define STAGE_B (4 * A_TILE_B)    // 65536 B: [A_h][A_m][B_h][B_m]
#define NSTAGE 3
#define DSMB (NSTAGE * STAGE_B + 1024)
#define HS_STRIDE 132

#define SC1 0.00048828125f            // 2^-11
#define SC2 2.384185791015625e-07f    // 2^-22

#define SWZ(off) ((off) ^ (((off) >> 3) & 0x70))

// ------------------------- device scratch buffers --------------------------
__device__ __align__(16) fp16  g_l0A[2ll * BATCH * 1024];   // state planes h,m
__device__ __align__(16) fp16  g_l0B[2ll * HCOLS * 1024];   // W0_0 planes h,m
__device__ __align__(16) fp16  g_l1A[(long)BATCH * UNITS];  // a0 (exact fp16)
__device__ __align__(16) fp16  g_l1B[2ll * HCOLS * UNITS];  // W0_1 planes h,m
__device__ __align__(16) float g_a1[(long)BATCH * UNITS];   // a1 fp32 for policy

// ------------------------------ helpers ------------------------------------
__device__ __forceinline__ unsigned smem_u32(const void* p) {
    unsigned a;
    asm("{ .reg .u64 t; cvta.to.shared.u64 t, %1; cvt.u32.u64 %0, t; }"
        : "=r"(a) : "l"(p));
    return a;
}
__device__ __forceinline__ void cpa16(unsigned dst, const void* src) {
    asm volatile(
        "{ .reg .u64 g; cvta.to.global.u64 g, %1; "
        "cp.async.cg.shared.global [%0], [g], 16; }"
        :: "r"(dst), "l"(src) : "memory");
}
__device__ __forceinline__ void ldsm4(unsigned addr, unsigned& r0, unsigned& r1,
                                      unsigned& r2, unsigned& r3) {
    asm volatile("ldmatrix.sync.aligned.m8n8.x4.shared.b16 {%0,%1,%2,%3}, [%4];"
                 : "=r"(r0), "=r"(r1), "=r"(r2), "=r"(r3) : "r"(addr));
}
__device__ __forceinline__ void mma_fp16(float* d, const unsigned* a,
                                         unsigned b0, unsigned b1) {
    asm volatile(
        "mma.sync.aligned.m16n8k16.row.col.f32.f16.f16.f32 "
        "{%0,%1,%2,%3}, {%4,%5,%6,%7}, {%8,%9}, {%0,%1,%2,%3};"
        : "+f"(d[0]), "+f"(d[1]), "+f"(d[2]), "+f"(d[3])
        : "r"(a[0]), "r"(a[1]), "r"(a[2]), "r"(a[3]), "r"(b0), "r"(b1));
}

// ------------- fp32 -> 2x fp16 split (m-plane scaled by 2^11) --------------
__global__ __launch_bounds__(256) void split2_kernel(
    const float* __restrict__ src, fp16* __restrict__ p0,
    fp16* __restrict__ p1, int n4)
{
    int i = blockIdx.x * blockDim.x + threadIdx.x;
    if (i >= n4) return;
    float4 v = ((const float4*)src)[i];
    float xs[4] = {v.x, v.y, v.z, v.w};
    union { fp16 b[4]; uint2 u; } ph, pm;
#pragma unroll
    for (int j = 0; j < 4; j++) {
        float x = xs[j];
        fp16 h = __float2half_rn(x);
        float r = x - __half2float(h);            // exact (Sterbenz)
        fp16 m = __float2half_rn(r * 2048.0f);    // scaled: stays normal-range
        ph.b[j] = h; pm.b[j] = m;
    }
    ((uint2*)p0)[i] = ph.u;
    ((uint2*)p1)[i] = pm.u;
}

// ----------------- fused mma.sync coagent layer ----------------------------
// x = x_h + 2^-11 x_m (fp16 planes). Per 64-K chunk, three scale groups each
// into a fresh ch[][]: mm (*2^-22), then mh+hm (*2^-11), then hh (*1, LAST),
// merged into acc via fma/add (smallest first). 3-stage cp.async pipeline.
// 512 threads, 4x4 warp grid, 32x32 warp tile (regs fit 128 -> 16 warps/SM).
// Per-output-element FP op sequence bit-identical to the R14 kernel.
template <int KTOT, bool SPLIT_A, bool OUT_FP16>
__global__ __launch_bounds__(NTHR, 1) void coagent_mma_kernel(
    const fp16* __restrict__ A,    // plane p at A + p*BATCH*KTOT, [BATCH,KTOT]
    const fp16* __restrict__ B,    // plane p at B + p*HCOLS*KTOT, [HCOLS,KTOT]
    const float* __restrict__ b0,  // [HCOLS]
    const float* __restrict__ W1,  // [UNITS*64]
    const float* __restrict__ b1,  // [UNITS*8]
    const float* __restrict__ W2,  // [UNITS*128]
    const float* __restrict__ b2,  // [UNITS*16]
    void* __restrict__ aout)       // [BATCH, UNITS] fp16 or float
{
    extern __shared__ __align__(16) char dsm[];
    __shared__ float w1s[16 * 64];
    __shared__ float w2s[16 * 128];
    __shared__ float b0s[NTC];
    __shared__ float b1s[16 * 8];
    __shared__ float b2s[16 * 16];

    const int tid  = threadIdx.x;
    const int wid  = tid >> 5;
    const int lane = tid & 31;
    const int row0 = blockIdx.y * MT;
    const int col0 = blockIdx.x * NTC;
    const int u0g  = blockIdx.x * 16;      // 16 units per CTA tile

    // align dynamic smem to 1024B (keeps SWZ pattern phase-correct)
    unsigned dyn_u32  = smem_u32(dsm);
    unsigned base_u32 = (dyn_u32 + 1023u) & ~1023u;
    char* basep = dsm + (base_u32 - dyn_u32);

    const int APL = SPLIT_A ? 2 : 1;

    // preload epilogue weights/biases
    for (int i = tid; i < 16 * 64;  i += NTHR) w1s[i] = W1[u0g * 64  + i];
    for (int i = tid; i < 16 * 128; i += NTHR) w2s[i] = W2[u0g * 128 + i];
    if (tid < NTC)      b0s[tid] = b0[col0 + tid];
    if (tid < 16 * 8)   b1s[tid] = b1[u0g * 8  + tid];
    if (tid < 16 * 16)  b2s[tid] = b2[u0g * 16 + tid];

    // warp tiling: 4 (m) x 4 (n), warp tile 32x32
    const int wm = (wid >> 2) * 32;
    const int wn = (wid & 3) * 32;

    // ldmatrix lane address components
    const int a_row = (lane & 7) + ((lane >> 3) & 1) * 8;  // within m16 frag
    const int a_ko  = (lane >> 4) * 8;                     // 0 or 8
    const int b_n   = (lane & 7) + ((lane >> 4) & 1) * 8;  // within n16 pair
    const int b_ko  = ((lane >> 3) & 1) * 8;

    float acc[2][4][4];   // master accumulator (2 m-frags x 4 n-frags)
#pragma unroll
    for (int mi = 0; mi < 2; mi++)
#pragma unroll
        for (int nj = 0; nj < 4; nj++)
#pragma unroll
            for (int q = 0; q < 4; q++) acc[mi][nj][q] = 0.0f;

// issue cp.async copies for chunk (c) into stage (ss)
// tiles within stage: [0]=A_h [1]=A_m [2]=B_h [3]=B_m
#define ISSUE_CHUNK(c, ss) do {                                               \
    unsigned dstb_ = base_u32 + (ss) * STAGE_B;                               \
    _Pragma("unroll")                                                         \
    for (int p_ = 0; p_ < APL; p_++) {                                        \
        const fp16* src_ = A + (long)p_ * BATCH * KTOT                        \
                         + (long)row0 * KTOT + (c) * KC;                      \
        unsigned db_ = dstb_ + p_ * A_TILE_B;                                 \
        _Pragma("unroll")                                                     \
        for (int i_ = tid; i_ < MT * 8; i_ += NTHR) {                         \
            int r_ = i_ >> 3, c8_ = (i_ & 7) * 8;                             \
            cpa16(db_ + SWZ(r_ * 128 + c8_ * 2), src_ + (long)r_ * KTOT + c8_);\
        }                                                                     \
    }                                                                         \
    _Pragma("unroll")                                                         \
    for (int p_ = 0; p_ < 2; p_++) {                                          \
        const fp16* src_ = B + (long)p_ * HCOLS * KTOT                        \
                         + (long)col0 * KTOT + (c) * KC;                      \
        unsigned db_ = dstb_ + (2 + p_) * A_TILE_B;                           \
        _Pragma("unroll")                                                     \
        for (int i_ = tid; i_ < NTC * 8; i_ += NTHR) {                        \
            int r_ = i_ >> 3, c8_ = (i_ & 7) * 8;                             \
            cpa16(db_ + SWZ(r_ * 128 + c8_ * 2), src_ + (long)r_ * KTOT + c8_);\
        }                                                                     \
    }                                                                         \
    asm volatile("cp.async.commit_group;" ::: "memory");                      \
} while (0)

#define LOAD_A(t, k16, cb) do {                                               \
    _Pragma("unroll")                                                         \
    for (int mi_ = 0; mi_ < 2; mi_++) {                                       \
        unsigned addr_ = (cb) + (t) * A_TILE_B +                              \
            SWZ((wm + mi_ * 16 + a_row) * 128 + ((k16) * 16 + a_ko) * 2);     \
        ldsm4(addr_, af[mi_][0], af[mi_][1], af[mi_][2], af[mi_][3]);         \
    } } while (0)

#define LOAD_B(t, k16, cb) do {                                               \
    _Pragma("unroll")                                                         \
    for (int j_ = 0; j_ < 2; j_++) {                                          \
        unsigned addr_ = (cb) + (t) * A_TILE_B +                              \
            SWZ((wn + j_ * 16 + b_n) * 128 + ((k16) * 16 + b_ko) * 2);        \
        ldsm4(addr_, bfr[j_][0], bfr[j_][1], bfr[j_][2], bfr[j_][3]);         \
    } } while (0)

#define MMA_ALL do {                                                          \
    _Pragma("unroll")                                                         \
    for (int mi_ = 0; mi_ < 2; mi_++)                                         \
    _Pragma("unroll")                                                         \
        for (int nj_ = 0; nj_ < 4; nj_++)                                     \
            mma_fp16(ch[mi_][nj_], af[mi_],                                   \
                     bfr[nj_ >> 1][(nj_ & 1) * 2],                            \
                     bfr[nj_ >> 1][(nj_ & 1) * 2 + 1]);                       \
    } while (0)

#define CH_ZERO do {                                                          \
    _Pragma("unroll")                                                         \
    for (int mi_ = 0; mi_ < 2; mi_++)                                         \
    _Pragma("unroll")                                                         \
        for (int nj_ = 0; nj_ < 4; nj_++)                                     \
    _Pragma("unroll")                                                         \
            for (int q_ = 0; q_ < 4; q_++) ch[mi_][nj_][q_] = 0.0f;           \
    } while (0)

#define ACC_FMA(scale) do {                                                   \
    _Pragma("unroll")                                                         \
    for (int mi_ = 0; mi_ < 2; mi_++)                                         \
    _Pragma("unroll")                                                         \
        for (int nj_ = 0; nj_ < 4; nj_++)                                     \
    _Pragma("unroll")                                                         \
            for (int q_ = 0; q_ < 4; q_++)                                    \
                acc[mi_][nj_][q_] = fmaf(ch[mi_][nj_][q_], (scale),           \
                                         acc[mi_][nj_][q_]);                  \
    } while (0)

#define ACC_ADD do {                                                          \
    _Pragma("unroll")                                                         \
    for (int mi_ = 0; mi_ < 2; mi_++)                                         \
    _Pragma("unroll")                                                         \
        for (int nj_ = 0; nj_ < 4; nj_++)                                     \
    _Pragma("unroll")                                                         \
            for (int q_ = 0; q_ < 4; q_++)                                    \
                acc[mi_][nj_][q_] += ch[mi_][nj_][q_];                        \
    } while (0)

    const int NCH = KTOT / KC;

    // prologue: stage chunks 0,1
    ISSUE_CHUNK(0, 0);
    if (NCH > 1) ISSUE_CHUNK(1, 1);

    for (int c = 0; c < NCH; ++c) {
        if (c + 1 < NCH)
            asm volatile("cp.async.wait_group 1;" ::: "memory");
        else
            asm volatile("cp.async.wait_group 0;" ::: "memory");
        __syncthreads();
        if (c + 2 < NCH) ISSUE_CHUNK(c + 2, (c + 2) % NSTAGE);

        const unsigned cb = base_u32 + (c % NSTAGE) * STAGE_B;

        float ch[2][4][4];
        unsigned af[2][4];    // A fragments (2 m16 frags)
        unsigned bfr[2][4];   // B fragments (2 n16 frags)

        if (SPLIT_A) {
            // group ss (*2^-22): mm
            CH_ZERO;
#pragma unroll
            for (int k16 = 0; k16 < KC / 16; k16++) {
                LOAD_A(1, k16, cb);
                LOAD_B(3, k16, cb);
                MMA_ALL;
            }
            ACC_FMA(SC2);
            // group s (*2^-11): mh then hm
            CH_ZERO;
#pragma unroll
            for (int k16 = 0; k16 < KC / 16; k16++) {
                LOAD_A(1, k16, cb);
                LOAD_B(2, k16, cb);
                MMA_ALL;
            }
#pragma unroll
            for (int k16 = 0; k16 < KC / 16; k16++) {
                LOAD_A(0, k16, cb);
                LOAD_B(3, k16, cb);
                MMA_ALL;
            }
            ACC_FMA(SC1);
            // main group: hh (last)
            CH_ZERO;
#pragma unroll
            for (int k16 = 0; k16 < KC / 16; k16++) {
                LOAD_A(0, k16, cb);
                LOAD_B(2, k16, cb);
                MMA_ALL;
            }
            ACC_ADD;
        } else {
            // A exact: group s (*2^-11): A*B_m
            CH_ZERO;
#pragma unroll
            for (int k16 = 0; k16 < KC / 16; k16++) {
                LOAD_A(0, k16, cb);
                LOAD_B(3, k16, cb);
                MMA_ALL;
            }
            ACC_FMA(SC1);
            // main group: A*B_h (last)
            CH_ZERO;
#pragma unroll
            for (int k16 = 0; k16 < KC / 16; k16++) {
                LOAD_A(0, k16, cb);
                LOAD_B(2, k16, cb);
                MMA_ALL;
            }
            ACC_ADD;
        }
    }
    __syncthreads();   // all ldmatrix reads done before hs overlay

    // scatter acc -> hs (bias + relu), HMMA d-frag layout
    float* hs = (float*)basep;     // [128][HS_STRIDE]
    {
        const int quad = lane >> 2, tq = lane & 3;
#pragma unroll
        for (int mi = 0; mi < 2; mi++) {
#pragma unroll
            for (int nj = 0; nj < 4; nj++) {
                int r = wm + mi * 16 + quad;
                int cc = wn + nj * 8 + tq * 2;
                hs[r * HS_STRIDE + cc]           = fmaxf(acc[mi][nj][0] + b0s[cc], 0.0f);
                hs[r * HS_STRIDE + cc + 1]       = fmaxf(acc[mi][nj][1] + b0s[cc + 1], 0.0f);
                hs[(r + 8) * HS_STRIDE + cc]     = fmaxf(acc[mi][nj][2] + b0s[cc], 0.0f);
                hs[(r + 8) * HS_STRIDE + cc + 1] = fmaxf(acc[mi][nj][3] + b0s[cc + 1], 0.0f);
            }
        }
    }
    __syncthreads();

    // tiny-MLP + argmax epilogue: 128 rows x 16 units = 2048 tasks
    for (int t = tid; t < 2048; t += NTHR) {
        const int row = t >> 4;
        const int uu  = t & 15;
        float hv[8];
        {
            float4 h0 = *(const float4*)&hs[row * HS_STRIDE + uu * 8];
            float4 h1 = *(const float4*)&hs[row * HS_STRIDE + uu * 8 + 4];
            hv[0] = h0.x; hv[1] = h0.y; hv[2] = h0.z; hv[3] = h0.w;
            hv[4] = h1.x; hv[5] = h1.y; hv[6] = h1.z; hv[7] = h1.w;
        }
        float h1v[8];
#pragma unroll
        for (int g = 0; g < 8; g++) {
            float s = b1s[uu * 8 + g];
#pragma unroll
            for (int h = 0; h < 8; h++) s += w1s[uu * 64 + g * 8 + h] * hv[h];
            h1v[g] = fmaxf(s, 0.0f);
        }
        float best = -3.402823466e38f;
        int   arg  = 0;
#pragma unroll
        for (int a = 0; a < NACT; a++) {
            float q = b2s[uu * 16 + a];
#pragma unroll
            for (int g = 0; g < 8; g++) q += w2s[uu * 128 + a * 8 + g] * h1v[g];
            if (q > best) { best = q; arg = a; }   // strict >: first max
        }
        if (OUT_FP16)
            ((fp16*)aout)[(long)(row0 + row) * UNITS + u0g + uu] = __float2half_rn((float)arg);
        else
            ((float*)aout)[(long)(row0 + row) * UNITS + u0g + uu] = (float)arg;
    }
}

// ------------------------------ policy head --------------------------------
__global__ __launch_bounds__(256) void policy_kernel(
    const float* __restrict__ a1, const float* __restrict__ PW0,
    const float* __restrict__ Pb0, const float* __restrict__ PW1,
    const float* __restrict__ Pb1, const float* __restrict__ PW2,
    const float* __restrict__ Pb2, float* __restrict__ out)
{
    const int lane = threadIdx.x & 31;
    const int row  = (blockIdx.x * blockDim.x + threadIdx.x) >> 5;
    if (row >= BATCH) return;
    const float* ar = a1 + (long)row * UNITS;
    float av[8];
    {
        float4 v0 = *(const float4*)&ar[lane * 8];
        float4 v1 = *(const float4*)&ar[lane * 8 + 4];
        av[0] = v0.x; av[1] = v0.y; av[2] = v0.z; av[3] = v0.w;
        av[4] = v1.x; av[5] = v1.y; av[6] = v1.z; av[7] = v1.w;
    }
    float hp[8];
#pragma unroll
    for (int j = 0; j < 8; j++) {
        float s = 0.0f;
#pragma unroll
        for (int i = 0; i < 8; i++) s += PW0[j * UNITS + lane * 8 + i] * av[i];
#pragma unroll
        for (int off = 16; off; off >>= 1) s += __shfl_xor_sync(0xffffffffu, s, off);
        hp[j] = s;
    }
    if (lane == 0) {
        float h0v[8], h1v[8];
#pragma unroll
        for (int j = 0; j < 8; j++) h0v[j] = fmaxf(hp[j] + Pb0[j], 0.0f);
#pragma unroll
        for (int j = 0; j < 8; j++) {
            float s = Pb1[j];
#pragma unroll
            for (int i = 0; i < 8; i++) s += PW1[j * 8 + i] * h0v[i];
            h1v[j] = fmaxf(s, 0.0f);
        }
        float o = Pb2[0];
#pragma unroll
        for (int i = 0; i < 8; i++) o += PW2[i] * h1v[i];
        out[row] = o;
    }
}

// ------------------------------- launcher ----------------------------------
extern "C" void kernel_launch(void* const* d_in, const int* in_sizes, int n_in,
                              void* d_out, int out_size) {
    (void)in_sizes; (void)n_in; (void)out_size;
    const float* state = (const float*)d_in[0];
    const float* W0_0  = (const float*)d_in[1];
    const float* b0_0  = (const float*)d_in[2];
    const float* W1_0  = (const float*)d_in[3];
    const float* b1_0  = (const float*)d_in[4];
    const float* W2_0  = (const float*)d_in[5];
    const float* b2_0  = (const float*)d_in[6];
    const float* W0_1  = (const float*)d_in[7];
    const float* b0_1  = (const float*)d_in[8];
    const float* W1_1  = (const float*)d_in[9];
    const float* b1_1  = (const float*)d_in[10];
    const float* W2_1  = (const float*)d_in[11];
    const float* b2_1  = (const float*)d_in[12];
    const float* PW0   = (const float*)d_in[13];
    const float* Pb0   = (const float*)d_in[14];
    const float* PW1   = (const float*)d_in[15];
    const float* Pb1   = (const float*)d_in[16];
    const float* PW2   = (const float*)d_in[17];
    const float* Pb2   = (const float*)d_in[18];
    float* out = (float*)d_out;

    fp16 *l0A, *l0B, *l1A, *l1B;
    float* a1;
    cudaGetSymbolAddress((void**)&l0A, g_l0A);
    cudaGetSymbolAddress((void**)&l0B, g_l0B);
    cudaGetSymbolAddress((void**)&l1A, g_l1A);
    cudaGetSymbolAddress((void**)&l1B, g_l1B);
    cudaGetSymbolAddress((void**)&a1,  g_a1);

    static int attr_done = 0;
    if (!attr_done) {
        cudaFuncSetAttribute(coagent_mma_kernel<1024, true, true>,
                             cudaFuncAttributeMaxDynamicSharedMemorySize, DSMB);
        cudaFuncSetAttribute(coagent_mma_kernel<256, false, false>,
                             cudaFuncAttributeMaxDynamicSharedMemorySize, DSMB);
        attr_done = 1;
    }

    // split fp32 -> 2 fp16 planes (m-plane scaled by 2^11)
    {
        int n4 = BATCH * 1024 / 4;
        split2_kernel<<<(n4 + 255) / 256, 256>>>(
            state, l0A, l0A + (long)BATCH * 1024, n4);
    }
    {
        int n4 = HCOLS * 1024 / 4;
        split2_kernel<<<(n4 + 255) / 256, 256>>>(
            W0_0, l0B, l0B + (long)HCOLS * 1024, n4);
    }
    {
        int n4 = HCOLS * UNITS / 4;
        split2_kernel<<<(n4 + 255) / 256, 256>>>(
            W0_1, l1B, l1B + (long)HCOLS * UNITS, n4);
    }

    dim3 grid(HCOLS / NTC, BATCH / MT);   // (16, 64)
    coagent_mma_kernel<1024, true, true><<<grid, NTHR, DSMB>>>(
        l0A, l0B, b0_0, W1_0, b1_0, W2_0, b2_0, (void*)l1A);
    coagent_mma_kernel<256, false, false><<<grid, NTHR, DSMB>>>(
        l1A, l1B, b0_1, W1_1, b1_1, W2_1, b2_1, (void*)a1);
    policy_kernel<<<BATCH * 32 / 256, 256>>>(a1, PW0, Pb0, PW1, Pb1, PW2, Pb2, out);
}

// round 17
// speedup vs baseline: 1.8967x; 1.8967x over previous
#include <cuda_runtime.h>
#include <cuda_fp16.h>
#include <cstdint>

typedef __half fp16;

#define BATCH 8192
#define UNITS 256
#define NACT  16
#define HID   8
#define HCOLS (UNITS * HID)   // 2048

#define MT 128        // batch rows per CTA
#define NTC 128       // h-cols per CTA
#define KC 64         // k per chunk
#define A_TILE_B (MT * KC * 2)    // 16384 B per tile
#define STAGE_B (4 * A_TILE_B)    // 65536 B: [A_h][A_m][B_h][B_m]
#define NSTAGE 3
#define DSMB (NSTAGE * STAGE_B + 1024)
#define HS_STRIDE 132

#define SC1 0.00048828125f            // 2^-11

#define SWZ(off) ((off) ^ (((off) >> 3) & 0x70))

// ------------------------- device scratch buffers --------------------------
__device__ __align__(16) fp16  g_l0A[2ll * BATCH * 1024];   // state planes h,m
__device__ __align__(16) fp16  g_l0B[2ll * HCOLS * 1024];   // W0_0 planes h,m
__device__ __align__(16) fp16  g_l1A[(long)BATCH * UNITS];  // a0 (exact fp16)
__device__ __align__(16) fp16  g_l1B[2ll * HCOLS * UNITS];  // W0_1 planes h,m
__device__ __align__(16) float g_a1[(long)BATCH * UNITS];   // a1 fp32 for policy

// ------------------------------ helpers ------------------------------------
__device__ __forceinline__ unsigned smem_u32(const void* p) {
    unsigned a;
    asm("{ .reg .u64 t; cvta.to.shared.u64 t, %1; cvt.u32.u64 %0, t; }"
        : "=r"(a) : "l"(p));
    return a;
}
__device__ __forceinline__ void cpa16(unsigned dst, const void* src) {
    asm volatile(
        "{ .reg .u64 g; cvta.to.global.u64 g, %1; "
        "cp.async.cg.shared.global [%0], [g], 16; }"
        :: "r"(dst), "l"(src) : "memory");
}
__device__ __forceinline__ void ldsm4(unsigned addr, unsigned& r0, unsigned& r1,
                                      unsigned& r2, unsigned& r3) {
    asm volatile("ldmatrix.sync.aligned.m8n8.x4.shared.b16 {%0,%1,%2,%3}, [%4];"
                 : "=r"(r0), "=r"(r1), "=r"(r2), "=r"(r3) : "r"(addr));
}
__device__ __forceinline__ void mma_fp16(float* d, const unsigned* a,
                                         unsigned b0, unsigned b1) {
    asm volatile(
        "mma.sync.aligned.m16n8k16.row.col.f32.f16.f16.f32 "
        "{%0,%1,%2,%3}, {%4,%5,%6,%7}, {%8,%9}, {%0,%1,%2,%3};"
        : "+f"(d[0]), "+f"(d[1]), "+f"(d[2]), "+f"(d[3])
        : "r"(a[0]), "r"(a[1]), "r"(a[2]), "r"(a[3]), "r"(b0), "r"(b1));
}

// ------------- fp32 -> 2x fp16 split (m-plane scaled by 2^11) --------------
__global__ __launch_bounds__(256) void split2_kernel(
    const float* __restrict__ src, fp16* __restrict__ p0,
    fp16* __restrict__ p1, int n4)
{
    int i = blockIdx.x * blockDim.x + threadIdx.x;
    if (i >= n4) return;
    float4 v = ((const float4*)src)[i];
    float xs[4] = {v.x, v.y, v.z, v.w};
    union { fp16 b[4]; uint2 u; } ph, pm;
#pragma unroll
    for (int j = 0; j < 4; j++) {
        float x = xs[j];
        fp16 h = __float2half_rn(x);
        float r = x - __half2float(h);            // exact (Sterbenz)
        fp16 m = __float2half_rn(r * 2048.0f);    // scaled: stays normal-range
        ph.b[j] = h; pm.b[j] = m;
    }
    ((uint2*)p0)[i] = ph.u;
    ((uint2*)p1)[i] = pm.u;
}

// ----------------- fused mma.sync coagent layer ----------------------------
// x = x_h + 2^-11 x_m (fp16 planes). Per 64-K chunk, two scale groups each
// into a fresh ch[][]: (mh + hm) (*2^-11), then hh (*1, LAST), merged into
// acc via fma/add (smallest first). mm pair (2^-22-scale) dropped: its
// contribution (~2.4e-7 rel) is below the accumulation error already present.
// 3-stage cp.async pipeline, 256 threads, 2x4 warp grid, 64x32 warp tile.
template <int KTOT, bool SPLIT_A, bool OUT_FP16>
__global__ __launch_bounds__(256, 1) void coagent_mma_kernel(
    const fp16* __restrict__ A,    // plane p at A + p*BATCH*KTOT, [BATCH,KTOT]
    const fp16* __restrict__ B,    // plane p at B + p*HCOLS*KTOT, [HCOLS,KTOT]
    const float* __restrict__ b0,  // [HCOLS]
    const float* __restrict__ W1,  // [UNITS*64]
    const float* __restrict__ b1,  // [UNITS*8]
    const float* __restrict__ W2,  // [UNITS*128]
    const float* __restrict__ b2,  // [UNITS*16]
    void* __restrict__ aout)       // [BATCH, UNITS] fp16 or float
{
    extern __shared__ __align__(16) char dsm[];
    __shared__ float w1s[16 * 64];
    __shared__ float w2s[16 * 128];
    __shared__ float b0s[NTC];
    __shared__ float b1s[16 * 8];
    __shared__ float b2s[16 * 16];

    const int tid  = threadIdx.x;
    const int wid  = tid >> 5;
    const int lane = tid & 31;
    const int row0 = blockIdx.y * MT;
    const int col0 = blockIdx.x * NTC;
    const int u0g  = blockIdx.x * 16;      // 16 units per CTA tile

    // align dynamic smem to 1024B (keeps SWZ pattern phase-correct)
    unsigned dyn_u32  = smem_u32(dsm);
    unsigned base_u32 = (dyn_u32 + 1023u) & ~1023u;
    char* basep = dsm + (base_u32 - dyn_u32);

    const int APL = SPLIT_A ? 2 : 1;

    // preload epilogue weights/biases
    for (int i = tid; i < 16 * 64;  i += 256) w1s[i] = W1[u0g * 64  + i];
    for (int i = tid; i < 16 * 128; i += 256) w2s[i] = W2[u0g * 128 + i];
    if (tid < NTC)      b0s[tid] = b0[col0 + tid];
    if (tid < 16 * 8)   b1s[tid] = b1[u0g * 8  + tid];
    if (tid < 16 * 16)  b2s[tid] = b2[u0g * 16 + tid];

    // warp tiling: 2 (m) x 4 (n), warp tile 64x32
    const int wm = (wid >> 2) * 64;
    const int wn = (wid & 3) * 32;

    // ldmatrix lane address components
    const int a_row = (lane & 7) + ((lane >> 3) & 1) * 8;  // within m16 frag
    const int a_ko  = (lane >> 4) * 8;                     // 0 or 8
    const int b_n   = (lane & 7) + ((lane >> 4) & 1) * 8;  // within n16 pair
    const int b_ko  = ((lane >> 3) & 1) * 8;

    float acc[4][4][4];   // master accumulator
#pragma unroll
    for (int mi = 0; mi < 4; mi++)
#pragma unroll
        for (int nj = 0; nj < 4; nj++)
#pragma unroll
            for (int q = 0; q < 4; q++) acc[mi][nj][q] = 0.0f;

// issue cp.async copies for chunk (c) into stage (ss)
// tiles within stage: [0]=A_h [1]=A_m [2]=B_h [3]=B_m
#define ISSUE_CHUNK(c, ss) do {                                               \
    unsigned dstb_ = base_u32 + (ss) * STAGE_B;                               \
    _Pragma("unroll")                                                         \
    for (int p_ = 0; p_ < APL; p_++) {                                        \
        const fp16* src_ = A + (long)p_ * BATCH * KTOT                        \
                         + (long)row0 * KTOT + (c) * KC;                      \
        unsigned db_ = dstb_ + p_ * A_TILE_B;                                 \
        _Pragma("unroll")                                                     \
        for (int i_ = tid; i_ < MT * 8; i_ += 256) {                          \
            int r_ = i_ >> 3, c8_ = (i_ & 7) * 8;                             \
            cpa16(db_ + SWZ(r_ * 128 + c8_ * 2), src_ + (long)r_ * KTOT + c8_);\
        }                                                                     \
    }                                                                         \
    _Pragma("unroll")                                                         \
    for (int p_ = 0; p_ < 2; p_++) {                                          \
        const fp16* src_ = B + (long)p_ * HCOLS * KTOT                        \
                         + (long)col0 * KTOT + (c) * KC;                      \
        unsigned db_ = dstb_ + (2 + p_) * A_TILE_B;                           \
        _Pragma("unroll")                                                     \
        for (int i_ = tid; i_ < NTC * 8; i_ += 256) {                         \
            int r_ = i_ >> 3, c8_ = (i_ & 7) * 8;                             \
            cpa16(db_ + SWZ(r_ * 128 + c8_ * 2), src_ + (long)r_ * KTOT + c8_);\
        }                                                                     \
    }                                                                         \
    asm volatile("cp.async.commit_group;" ::: "memory");                      \
} while (0)

#define LOAD_A(dst, t, k16, cb) do {                                          \
    _Pragma("unroll")                                                         \
    for (int mi_ = 0; mi_ < 4; mi_++) {                                       \
        unsigned addr_ = (cb) + (t) * A_TILE_B +                              \
            SWZ((wm + mi_ * 16 + a_row) * 128 + ((k16) * 16 + a_ko) * 2);     \
        ldsm4(addr_, (dst)[mi_][0], (dst)[mi_][1], (dst)[mi_][2], (dst)[mi_][3]);\
    } } while (0)

#define LOAD_B(dst, t, k16, cb) do {                                          \
    _Pragma("unroll")                                                         \
    for (int j_ = 0; j_ < 2; j_++) {                                          \
        unsigned addr_ = (cb) + (t) * A_TILE_B +                              \
            SWZ((wn + j_ * 16 + b_n) * 128 + ((k16) * 16 + b_ko) * 2);        \
        ldsm4(addr_, (dst)[j_][0], (dst)[j_][1], (dst)[j_][2], (dst)[j_][3]); \
    } } while (0)

#define MMA_ALL(afx, bfx) do {                                                \
    _Pragma("unroll")                                                         \
    for (int mi_ = 0; mi_ < 4; mi_++)                                         \
    _Pragma("unroll")                                                         \
        for (int nj_ = 0; nj_ < 4; nj_++)                                     \
            mma_fp16(ch[mi_][nj_], (afx)[mi_],                                \
                     (bfx)[nj_ >> 1][(nj_ & 1) * 2],                          \
                     (bfx)[nj_ >> 1][(nj_ & 1) * 2 + 1]);                     \
    } while (0)

#define CH_ZERO do {                                                          \
    _Pragma("unroll")                                                         \
    for (int mi_ = 0; mi_ < 4; mi_++)                                         \
    _Pragma("unroll")                                                         \
        for (int nj_ = 0; nj_ < 4; nj_++)                                     \
    _Pragma("unroll")                                                         \
            for (int q_ = 0; q_ < 4; q_++) ch[mi_][nj_][q_] = 0.0f;           \
    } while (0)

#define ACC_FMA(scale) do {                                                   \
    _Pragma("unroll")                                                         \
    for (int mi_ = 0; mi_ < 4; mi_++)                                         \
    _Pragma("unroll")                                                         \
        for (int nj_ = 0; nj_ < 4; nj_++)                                     \
    _Pragma("unroll")                                                         \
            for (int q_ = 0; q_ < 4; q_++)                                    \
                acc[mi_][nj_][q_] = fmaf(ch[mi_][nj_][q_], (scale),           \
                                         acc[mi_][nj_][q_]);                  \
    } while (0)

#define ACC_ADD do {                                                          \
    _Pragma("unroll")                                                         \
    for (int mi_ = 0; mi_ < 4; mi_++)                                         \
    _Pragma("unroll")                                                         \
        for (int nj_ = 0; nj_ < 4; nj_++)                                     \
    _Pragma("unroll")                                                         \
            for (int q_ = 0; q_ < 4; q_++)                                    \
                acc[mi_][nj_][q_] += ch[mi_][nj_][q_];                        \
    } while (0)

    const int NCH = KTOT / KC;

    // prologue: stage chunks 0,1
    ISSUE_CHUNK(0, 0);
    if (NCH > 1) ISSUE_CHUNK(1, 1);

    for (int c = 0; c < NCH; ++c) {
        if (c + 1 < NCH)
            asm volatile("cp.async.wait_group 1;" ::: "memory");
        else
            asm volatile("cp.async.wait_group 0;" ::: "memory");
        __syncthreads();
        if (c + 2 < NCH) ISSUE_CHUNK(c + 2, (c + 2) % NSTAGE);

        const unsigned cb = base_u32 + (c % NSTAGE) * STAGE_B;

        float ch[4][4][4];
        unsigned af[2][4][4];    // A fragments, double-buffered by k16 parity
        unsigned bfr[2][2][4];   // B fragments, alternating sets

        if (SPLIT_A) {
            // group s (*2^-11): mh then hm (mm pair dropped: 2^-22-scale)
            CH_ZERO;
#pragma unroll
            for (int k16 = 0; k16 < KC / 16; k16++) {
                LOAD_A(af[k16 & 1], 1, k16, cb);
                LOAD_B(bfr[k16 & 1], 2, k16, cb);
                MMA_ALL(af[k16 & 1], bfr[k16 & 1]);
            }
#pragma unroll
            for (int k16 = 0; k16 < KC / 16; k16++) {
                LOAD_A(af[k16 & 1], 0, k16, cb);
                LOAD_B(bfr[k16 & 1], 3, k16, cb);
                MMA_ALL(af[k16 & 1], bfr[k16 & 1]);
            }
            ACC_FMA(SC1);
            // main group: hh (last)
            CH_ZERO;
#pragma unroll
            for (int k16 = 0; k16 < KC / 16; k16++) {
                LOAD_A(af[k16 & 1], 0, k16, cb);
                LOAD_B(bfr[k16 & 1], 2, k16, cb);
                MMA_ALL(af[k16 & 1], bfr[k16 & 1]);
            }
            ACC_ADD;
        } else {
            // A exact: group s (*2^-11): A*B_m
            CH_ZERO;
#pragma unroll
            for (int k16 = 0; k16 < KC / 16; k16++) {
                LOAD_A(af[k16 & 1], 0, k16, cb);
                LOAD_B(bfr[k16 & 1], 3, k16, cb);
                MMA_ALL(af[k16 & 1], bfr[k16 & 1]);
            }
            ACC_FMA(SC1);
            // main group: A*B_h (last)
            CH_ZERO;
#pragma unroll
            for (int k16 = 0; k16 < KC / 16; k16++) {
                LOAD_A(af[k16 & 1], 0, k16, cb);
                LOAD_B(bfr[k16 & 1], 2, k16, cb);
                MMA_ALL(af[k16 & 1], bfr[k16 & 1]);
            }
            ACC_ADD;
        }
    }
    __syncthreads();   // all ldmatrix reads done before hs overlay

    // scatter acc -> hs (bias + relu), HMMA d-frag layout
    float* hs = (float*)basep;     // [128][HS_STRIDE]
    {
        const int quad = lane >> 2, tq = lane & 3;
#pragma unroll
        for (int mi = 0; mi < 4; mi++) {
#pragma unroll
            for (int nj = 0; nj < 4; nj++) {
                int r = wm + mi * 16 + quad;
                int cc = wn + nj * 8 + tq * 2;
                hs[r * HS_STRIDE + cc]           = fmaxf(acc[mi][nj][0] + b0s[cc], 0.0f);
                hs[r * HS_STRIDE + cc + 1]       = fmaxf(acc[mi][nj][1] + b0s[cc + 1], 0.0f);
                hs[(r + 8) * HS_STRIDE + cc]     = fmaxf(acc[mi][nj][2] + b0s[cc], 0.0f);
                hs[(r + 8) * HS_STRIDE + cc + 1] = fmaxf(acc[mi][nj][3] + b0s[cc + 1], 0.0f);
            }
        }
    }
    __syncthreads();

    // tiny-MLP + argmax epilogue: 128 rows x 16 units = 2048 tasks
    for (int t = tid; t < 2048; t += 256) {
        const int row = t >> 4;
        const int uu  = t & 15;
        float hv[8];
        {
            float4 h0 = *(const float4*)&hs[row * HS_STRIDE + uu * 8];
            float4 h1 = *(const float4*)&hs[row * HS_STRIDE + uu * 8 + 4];
            hv[0] = h0.x; hv[1] = h0.y; hv[2] = h0.z; hv[3] = h0.w;
            hv[4] = h1.x; hv[5] = h1.y; hv[6] = h1.z; hv[7] = h1.w;
        }
        float h1v[8];
#pragma unroll
        for (int g = 0; g < 8; g++) {
            float s = b1s[uu * 8 + g];
#pragma unroll
            for (int h = 0; h < 8; h++) s += w1s[uu * 64 + g * 8 + h] * hv[h];
            h1v[g] = fmaxf(s, 0.0f);
        }
        float best = -3.402823466e38f;
        int   arg  = 0;
#pragma unroll
        for (int a = 0; a < NACT; a++) {
            float q = b2s[uu * 16 + a];
#pragma unroll
            for (int g = 0; g < 8; g++) q += w2s[uu * 128 + a * 8 + g] * h1v[g];
            if (q > best) { best = q; arg = a; }   // strict >: first max
        }
        if (OUT_FP16)
            ((fp16*)aout)[(long)(row0 + row) * UNITS + u0g + uu] = __float2half_rn((float)arg);
        else
            ((float*)aout)[(long)(row0 + row) * UNITS + u0g + uu] = (float)arg;
    }
}

// ------------------------------ policy head --------------------------------
__global__ __launch_bounds__(256) void policy_kernel(
    const float* __restrict__ a1, const float* __restrict__ PW0,
    const float* __restrict__ Pb0, const float* __restrict__ PW1,
    const float* __restrict__ Pb1, const float* __restrict__ PW2,
    const float* __restrict__ Pb2, float* __restrict__ out)
{
    const int lane = threadIdx.x & 31;
    const int row  = (blockIdx.x * blockDim.x + threadIdx.x) >> 5;
    if (row >= BATCH) return;
    const float* ar = a1 + (long)row * UNITS;
    float av[8];
    {
        float4 v0 = *(const float4*)&ar[lane * 8];
        float4 v1 = *(const float4*)&ar[lane * 8 + 4];
        av[0] = v0.x; av[1] = v0.y; av[2] = v0.z; av[3] = v0.w;
        av[4] = v1.x; av[5] = v1.y; av[6] = v1.z; av[7] = v1.w;
    }
    float hp[8];
#pragma unroll
    for (int j = 0; j < 8; j++) {
        float s = 0.0f;
#pragma unroll
        for (int i = 0; i < 8; i++) s += PW0[j * UNITS + lane * 8 + i] * av[i];
#pragma unroll
        for (int off = 16; off; off >>= 1) s += __shfl_xor_sync(0xffffffffu, s, off);
        hp[j] = s;
    }
    if (lane == 0) {
        float h0v[8], h1v[8];
#pragma unroll
        for (int j = 0; j < 8; j++) h0v[j] = fmaxf(hp[j] + Pb0[j], 0.0f);
#pragma unroll
        for (int j = 0; j < 8; j++) {
            float s = Pb1[j];
#pragma unroll
            for (int i = 0; i < 8; i++) s += PW1[j * 8 + i] * h0v[i];
            h1v[j] = fmaxf(s, 0.0f);
        }
        float o = Pb2[0];
#pragma unroll
        for (int i = 0; i < 8; i++) o += PW2[i] * h1v[i];
        out[row] = o;
    }
}

// ------------------------------- launcher ----------------------------------
extern "C" void kernel_launch(void* const* d_in, const int* in_sizes, int n_in,
                              void* d_out, int out_size) {
    (void)in_sizes; (void)n_in; (void)out_size;
    const float* state = (const float*)d_in[0];
    const float* W0_0  = (const float*)d_in[1];
    const float* b0_0  = (const float*)d_in[2];
    const float* W1_0  = (const float*)d_in[3];
    const float* b1_0  = (const float*)d_in[4];
    const float* W2_0  = (const float*)d_in[5];
    const float* b2_0  = (const float*)d_in[6];
    const float* W0_1  = (const float*)d_in[7];
    const float* b0_1  = (const float*)d_in[8];
    const float* W1_1  = (const float*)d_in[9];
    const float* b1_1  = (const float*)d_in[10];
    const float* W2_1  = (const float*)d_in[11];
    const float* b2_1  = (const float*)d_in[12];
    const float* PW0   = (const float*)d_in[13];
    const float* Pb0   = (const float*)d_in[14];
    const float* PW1   = (const float*)d_in[15];
    const float* Pb1   = (const float*)d_in[16];
    const float* PW2   = (const float*)d_in[17];
    const float* Pb2   = (const float*)d_in[18];
    float* out = (float*)d_out;

    fp16 *l0A, *l0B, *l1A, *l1B;
    float* a1;
    cudaGetSymbolAddress((void**)&l0A, g_l0A);
    cudaGetSymbolAddress((void**)&l0B, g_l0B);
    cudaGetSymbolAddress((void**)&l1A, g_l1A);
    cudaGetSymbolAddress((void**)&l1B, g_l1B);
    cudaGetSymbolAddress((void**)&a1,  g_a1);

    static int attr_done = 0;
    if (!attr_done) {
        cudaFuncSetAttribute(coagent_mma_kernel<1024, true, true>,
                             cudaFuncAttributeMaxDynamicSharedMemorySize, DSMB);
        cudaFuncSetAttribute(coagent_mma_kernel<256, false, false>,
                             cudaFuncAttributeMaxDynamicSharedMemorySize, DSMB);
        attr_done = 1;
    }

    // split fp32 -> 2 fp16 planes (m-plane scaled by 2^11)
    {
        int n4 = BATCH * 1024 / 4;
        split2_kernel<<<(n4 + 255) / 256, 256>>>(
            state, l0A, l0A + (long)BATCH * 1024, n4);
    }
    {
        int n4 = HCOLS * 1024 / 4;
        split2_kernel<<<(n4 + 255) / 256, 256>>>(
            W0_0, l0B, l0B + (long)HCOLS * 1024, n4);
    }
    {
        int n4 = HCOLS * UNITS / 4;
        split2_kernel<<<(n4 + 255) / 256, 256>>>(
            W0_1, l1B, l1B + (long)HCOLS * UNITS, n4);
    }

    dim3 grid(HCOLS / NTC, BATCH / MT);   // (16, 64)
    coagent_mma_kernel<1024, true, true><<<grid, 256, DSMB>>>(
        l0A, l0B, b0_0, W1_0, b1_0, W2_0, b2_0, (void*)l1A);
    coagent_mma_kernel<256, false, false><<<grid, 256, DSMB>>>(
        l1A, l1B, b0_1, W1_1, b1_1, W2_1, b2_1, (void*)a1);
    policy_kernel<<<BATCH * 32 / 256, 256>>>(a1, PW0, Pb0, PW1, Pb1, PW2, Pb2, out);
}